// round 17
// baseline (speedup 1.0000x reference)
#include <cuda_runtime.h>
#include <cuda_bf16.h>
#include <cstdint>

#define DEV_INLINE __device__ __forceinline__

// ---------------- problem sizes (fixed) ----------------
#define DD    2048
#define SD    512
#define MROWS 16384          // B*N = 4*4096
#define KTOT  4096           // concatenated K (attn 2048 | hyb 2048)
#define BK    64             // K elements per pipeline chunk (bf16)
#define NK_CHUNKS 64         // 4096/64
#define STAGES 3
#define STAGE_BYTES 32768    // A tile 16KB + B tile 16KB
#define AUX_BYTES 1024       // bias(128f) + Rw(16f) + scratch
#define DYN_SMEM (STAGES * STAGE_BYTES + AUX_BYTES)
#define WT_BLOCKS 2048       // 64 kblk * 16 ddblk * 2 z

// ---------------- device scratch (static, no allocs) ----------------
__device__ __nv_bfloat16 g_A [(size_t)MROWS * KTOT];  // [m][attn 0..2047 | hyb 2048..4095]
__device__ __nv_bfloat16 g_Wc[(size_t)DD * KTOT];     // permuted combined weights [p][k]

// ---------------- PTX helpers (base ISA only: sm_80+) ----------------
DEV_INLINE uint32_t smem_u32(const void* p) {
    uint32_t a;
    asm("{ .reg .u64 t; cvta.to.shared.u64 t, %1; cvt.u32.u64 %0, t; }" : "=r"(a) : "l"(p));
    return a;
}
#define SW128(o) ((o) ^ ((((uint32_t)(o)) >> 3) & 0x70u))

DEV_INLINE void cp_async16(uint32_t dst, const void* src) {
    asm volatile("cp.async.cg.shared.global [%0], [%1], 16;" :: "r"(dst), "l"(src));
}
DEV_INLINE void cp_commit() { asm volatile("cp.async.commit_group;" ::: "memory"); }
template<int N> DEV_INLINE void cp_wait() {
    asm volatile("cp.async.wait_group %0;" :: "n"(N) : "memory");
}
DEV_INLINE void ldm_x4(uint32_t* r, uint32_t addr) {
    asm volatile("ldmatrix.sync.aligned.m8n8.x4.shared.b16 {%0,%1,%2,%3}, [%4];"
                 : "=r"(r[0]), "=r"(r[1]), "=r"(r[2]), "=r"(r[3]) : "r"(addr));
}
DEV_INLINE void mma16816(float* d, const uint32_t* a, uint32_t b0, uint32_t b1) {
    asm volatile(
        "mma.sync.aligned.m16n8k16.row.col.f32.bf16.bf16.f32 "
        "{%0,%1,%2,%3}, {%4,%5,%6,%7}, {%8,%9}, {%0,%1,%2,%3};"
        : "+f"(d[0]), "+f"(d[1]), "+f"(d[2]), "+f"(d[3])
        : "r"(a[0]), "r"(a[1]), "r"(a[2]), "r"(a[3]), "r"(b0), "r"(b1));
}

// ---------------- warp-parallel 4x4 matrix math ----------------
// ALL 32 lanes execute (lanes 16..31 mirror 0..15); xor strides never cross halves.
DEV_INLINE float softmax16(float v) {           // softmax over low 2 bits of lane
    float mx = v;
    mx = fmaxf(mx, __shfl_xor_sync(0xffffffffu, mx, 1));
    mx = fmaxf(mx, __shfl_xor_sync(0xffffffffu, mx, 2));
    float e = expf(v - mx);
    float sum = e;
    sum += __shfl_xor_sync(0xffffffffu, sum, 1);
    sum += __shfl_xor_sync(0xffffffffu, sum, 2);
    return e / sum;
}
DEV_INLINE float sinkhorn16(float v) {          // rows = low 2 bits, cols = bits 2-3
    float mx = v;
    mx = fmaxf(mx, __shfl_xor_sync(0xffffffffu, mx, 1));
    mx = fmaxf(mx, __shfl_xor_sync(0xffffffffu, mx, 2));
    mx = fmaxf(mx, __shfl_xor_sync(0xffffffffu, mx, 4));
    mx = fmaxf(mx, __shfl_xor_sync(0xffffffffu, mx, 8));
    float p = expf(v - mx);
#pragma unroll
    for (int it = 0; it < 20; it++) {
        float rs = p;
        rs += __shfl_xor_sync(0xffffffffu, rs, 1);
        rs += __shfl_xor_sync(0xffffffffu, rs, 2);
        p *= 1.f / (rs + 1e-8f);
        float cs = p;
        cs += __shfl_xor_sync(0xffffffffu, cs, 4);
        cs += __shfl_xor_sync(0xffffffffu, cs, 8);
        p *= 1.f / (cs + 1e-8f);
    }
    return p;
}

// ---------------- fused prep: LayerNorm+H_pre rows AND W transform blocks ----------
DEV_INLINE uint32_t packbf2(float a, float b) {
    __nv_bfloat162 t = __floats2bfloat162_rn(a, b);
    return *reinterpret_cast<uint32_t*>(&t);
}
__global__ void __launch_bounds__(256) prep_kernel(
        const float* __restrict__ x,
        const float* __restrict__ gamma,
        const float* __restrict__ beta,
        const float* __restrict__ Wa,
        const float* __restrict__ Wh,
        const float* __restrict__ pa, const float* __restrict__ ph,
        const float* __restrict__ po_a, const float* __restrict__ sa,
        const float* __restrict__ po_h, const float* __restrict__ sh,
        const float* __restrict__ cm) {
    const int tid = threadIdx.x;
    const int lane = tid & 31;
    const int e = lane & 15;

    if (blockIdx.x >= MROWS) {
        // ---- W transform block ----
        __shared__ float t4[4][32][33];
        __shared__ float s_c[16];            // (z? ch_mix : ca_mix)[t*4+s]
        const int w = blockIdx.x - MROWS;
        const int kblk = w & 63;
        const int ddblk = (w >> 6) & 15;
        const int z = w >> 10;
        const float* W = z ? Wh : Wa;
        const int k0  = kblk * 32;
        const int dd0 = ddblk * 32;
        const int tx = lane, ty = tid >> 5;  // 32x8

        if (ty == 0) {                       // warp 0: coefficients (hidden by tile load)
            float sm = softmax16(z ? po_h[e] : po_a[e]);   // e = t*4+s
            float alpha = 1.f / (1.f + expf(-cm[0]));
            float coef = z ? (1.f - alpha) * sh[e >> 2] : alpha * sa[e >> 2];
            if (lane < 16) s_c[e] = coef * sm;
        }
#pragma unroll
        for (int s = 0; s < 4; s++)
#pragma unroll
            for (int j = 0; j < 32; j += 8)
                t4[s][ty + j][tx] = W[(size_t)(k0 + ty + j) * DD + s * SD + dd0 + tx];
        __syncthreads();
#pragma unroll
        for (int t = 0; t < 4; t++) {
            float c[4];
#pragma unroll
            for (int s = 0; s < 4; s++) c[s] = s_c[t * 4 + s];
            const size_t prow = (size_t)(ddblk * 128 + t * 32);
#pragma unroll
            for (int j = 0; j < 32; j += 8) {
                int pi = ty + j;
                float v = 0.f;
#pragma unroll
                for (int s = 0; s < 4; s++) v += c[s] * t4[s][tx][pi];
                g_Wc[(prow + pi) * KTOT + z * DD + k0 + tx] = __float2bfloat16(v);
            }
        }
        return;
    }

    // ---- LayerNorm + H_pre row ----
    __shared__ float sred[18];
    __shared__ float s_pa[16], s_ph[16];     // pre_a/pre_h [s*4+t]
    const float* xr = x + (size_t)blockIdx.x * DD;
    const int d0 = tid * 2;

    if ((tid >> 5) == 0) {                   // warp 0: H_pre softmaxes
        float va = softmax16(pa[e]);         // e = s*4+t, softmax over t
        float vh = softmax16(ph[e]);
        if (lane < 16) { s_pa[e] = va; s_ph[e] = vh; }
    }

    float2 xv[4];
    float s1 = 0.f, s2 = 0.f;
#pragma unroll
    for (int s = 0; s < 4; s++) {
        xv[s] = *(const float2*)(xr + s * SD + d0);
        s1 += xv[s].x + xv[s].y;
        s2 += xv[s].x * xv[s].x + xv[s].y * xv[s].y;
    }
#pragma unroll
    for (int off = 16; off > 0; off >>= 1) {
        s1 += __shfl_xor_sync(0xffffffffu, s1, off);
        s2 += __shfl_xor_sync(0xffffffffu, s2, off);
    }
    if ((tid & 31) == 0) { sred[tid >> 5] = s1; sred[8 + (tid >> 5)] = s2; }
    __syncthreads();
    if (tid == 0) {
        float a = 0.f, b = 0.f;
        for (int w = 0; w < 8; w++) { a += sred[w]; b += sred[8 + w]; }
        float mu = a * (1.f / DD);
        float var = b * (1.f / DD) - mu * mu;
        sred[16] = mu;
        sred[17] = rsqrtf(var + 1e-5f);
    }
    __syncthreads();
    const float mu = sred[16], rstd = sred[17];

    float n0[4], n1[4];
#pragma unroll
    for (int s = 0; s < 4; s++) {
        float2 gv = __ldg((const float2*)(gamma + s * SD + d0));
        float2 bv = __ldg((const float2*)(beta  + s * SD + d0));
        n0[s] = (xv[s].x - mu) * rstd * gv.x + bv.x;
        n1[s] = (xv[s].y - mu) * rstd * gv.y + bv.y;
    }

    __nv_bfloat16* arow = g_A + (size_t)blockIdx.x * KTOT;
#pragma unroll
    for (int t = 0; t < 4; t++) {
        float a0 = 0.f, a1 = 0.f, h0 = 0.f, h1 = 0.f;
#pragma unroll
        for (int s = 0; s < 4; s++) {
            float wa = s_pa[s * 4 + t];
            float wh = s_ph[s * 4 + t];
            a0 += wa * n0[s];  a1 += wa * n1[s];
            h0 += wh * xv[s].x; h1 += wh * xv[s].y;
        }
        *(uint32_t*)(arow + t * SD + d0)      = packbf2(a0, a1);  // attn half
        *(uint32_t*)(arow + DD + t * SD + d0) = packbf2(h0, h1);  // hyb half
    }
}

// ---------------- fused bf16 mma.sync GEMM + final epilogue ----------------
// CTA tile 128x128, 4 warps (2m x 2n), warp tile 64x64, BK=64, 3-stage cp.async,
// 2 CTAs/SM. Warp 0 computes Rw (Sinkhorn) + permuted bias into smem during the
// pipeline fill -> no separate small_kernel launch.
__global__ void __launch_bounds__(128, 2) gemm_kernel(
        const float* __restrict__ x, float* __restrict__ out,
        const float* __restrict__ ra, const float* __restrict__ rh,
        const float* __restrict__ po_a, const float* __restrict__ sa,
        const float* __restrict__ po_h, const float* __restrict__ sh,
        const float* __restrict__ cm,
        const float* __restrict__ ba, const float* __restrict__ bh) {
    extern __shared__ __align__(128) char dsm[];
    float* s_bias = (float*)(dsm + STAGES * STAGE_BYTES);          // [128]
    float* s_Rw   = s_bias + 128;                                   // [16] (s*4+t)

    const int tid  = threadIdx.x;
    const int wid  = tid >> 5;
    const int lane = tid & 31;
    const int nb = blockIdx.x, mbk = blockIdx.y;
    const int m0 = mbk * 128, n0 = nb * 128;
    const int dd0 = nb * 32;

    const uint32_t smem_base = smem_u32(dsm);

    const int lrow = tid >> 3;       // 0..15
    const int lcol = tid & 7;        // 0..7

    const int wm = wid & 1;          // 2 m-warps
    const int wn = wid >> 1;         // 2 n-warps
    const int mwarp = wm * 64, nwarp = wn * 64;

    const int lrow16 = lane & 15;
    const int lkhalf = (lane >> 4) * 16;

    const __nv_bfloat16* Abase = g_A  + (size_t)(m0 + lrow) * KTOT + lcol * 8;
    const __nv_bfloat16* Bbase = g_Wc + (size_t)(n0 + lrow) * KTOT + lcol * 8;

    auto load_stage = [&](uint32_t st, int chunk) {
        const __nv_bfloat16* Ap = Abase + chunk * BK;
        const __nv_bfloat16* Bp = Bbase + chunk * BK;
#pragma unroll
        for (int j = 0; j < 8; j++) {
            int r = lrow + 16 * j;
            cp_async16(st + SW128(r * 128 + lcol * 16), Ap + (size_t)(16 * j) * KTOT);
        }
#pragma unroll
        for (int j = 0; j < 8; j++) {
            int r = lrow + 16 * j;
            cp_async16(st + 16384 + SW128(r * 128 + lcol * 16), Bp + (size_t)(16 * j) * KTOT);
        }
        cp_commit();
    };

    uint32_t sCur  = smem_base;
    uint32_t sNext = smem_base + STAGE_BYTES;
    uint32_t sLoad = smem_base + 2 * STAGE_BYTES;

    load_stage(sCur, 0);
    load_stage(sNext, 1);

    // ---- warp 0: small-matrix math into smem, hidden behind pipeline fill ----
    if (wid == 0) {
        const int e = lane & 15;
        float alpha = 1.f / (1.f + expf(-cm[0]));
        float beta  = 1.f - alpha;
        float wra = sinkhorn16(ra[e]);               // e = s*4+t
        float wrh = sinkhorn16(rh[e]);
        if (lane < 16) s_Rw[e] = alpha * wra + beta * wrh;
        float sma = softmax16(po_a[e]);              // e = t*4+s
        float smh = softmax16(po_h[e]);
        float ca = alpha * sa[e >> 2] * sma;         // broadcast to whole warp via shfl below
        float ch = beta  * sh[e >> 2] * smh;
        // bias: lane l handles colT = q*32 + l (t = q, dd = dd0 + l)
#pragma unroll
        for (int q = 0; q < 4; q++) {
            float v = 0.f;
#pragma unroll
            for (int s = 0; s < 4; s++) {
                float cav = __shfl_sync(0xffffffffu, ca, q * 4 + s);
                float chv = __shfl_sync(0xffffffffu, ch, q * 4 + s);
                v += cav * __ldg(ba + s * SD + dd0 + lane)
                   + chv * __ldg(bh + s * SD + dd0 + lane);
            }
            s_bias[q * 32 + lane] = v;
        }
    }

    uint32_t af[2][4][4], bf[2][4][4];

    auto prefetch = [&](uint32_t stA, int ks, int buf) {
        const uint32_t stB = stA + 16384;
        const int kb = ks * 32 + lkhalf;
#pragma unroll
        for (int i = 0; i < 4; i++)
            ldm_x4(af[buf][i], stA + SW128((mwarp + i * 16 + lrow16) * 128 + kb));
#pragma unroll
        for (int j = 0; j < 4; j++)
            ldm_x4(bf[buf][j], stB + SW128((nwarp + j * 16 + lrow16) * 128 + kb));
    };

    float acc[4][8][4];
#pragma unroll
    for (int i = 0; i < 4; i++)
#pragma unroll
        for (int j = 0; j < 8; j++)
#pragma unroll
            for (int q = 0; q < 4; q++) acc[i][j][q] = 0.f;

    cp_wait<1>();          // chunk 0 ready
    __syncthreads();       // also publishes warp 0's s_bias / s_Rw
    prefetch(sCur, 0, 0);  // chunk 0, ks=0

    for (int c = 0; c < NK_CHUNKS; c++) {
        if (c + 2 < NK_CHUNKS) load_stage(sLoad, c + 2);

#pragma unroll
        for (int ks = 0; ks < 4; ks++) {
            const int cur = ks & 1, nxt = cur ^ 1;
            if (ks < 3) prefetch(sCur, ks + 1, nxt);
#pragma unroll
            for (int i = 0; i < 4; i++)
#pragma unroll
                for (int j = 0; j < 4; j++) {
                    mma16816(acc[i][j * 2 + 0], af[cur][i], bf[cur][j][0], bf[cur][j][2]);
                    mma16816(acc[i][j * 2 + 1], af[cur][i], bf[cur][j][1], bf[cur][j][3]);
                }
        }

        if (c + 1 < NK_CHUNKS) {
            if (c + 2 < NK_CHUNKS) cp_wait<1>(); else cp_wait<0>();
            __syncthreads();
            prefetch(sNext, 0, 0);
        }
        uint32_t t = sCur; sCur = sNext; sNext = sLoad; sLoad = t;
    }

    // fused epilogue: out = acc + bias~ + residual-mix of x.
    const int erow = lane >> 2;
    const int ecol = (lane & 3) * 2;
    const int tlo = nwarp >> 5;
#pragma unroll
    for (int j = 0; j < 4; j++) {
        const int colT = nwarp + j * 8 + ecol;
        const int dd = dd0 + (colT & 31);
        const float2 bv0 = *(const float2*)(s_bias + colT);
        const float2 bv1 = *(const float2*)(s_bias + colT + 32);
        float rw0[4], rw1[4];
#pragma unroll
        for (int s = 0; s < 4; s++) { rw0[s] = s_Rw[s * 4 + tlo]; rw1[s] = s_Rw[s * 4 + tlo + 1]; }
#pragma unroll
        for (int i = 0; i < 4; i++) {
#pragma unroll
            for (int rr = 0; rr < 2; rr++) {
                const int m = m0 + mwarp + i * 16 + erow + rr * 8;
                const float* xr = x + (size_t)m * DD + dd;
                float2 xv[4];
#pragma unroll
                for (int s = 0; s < 4; s++) xv[s] = __ldg((const float2*)(xr + s * SD));
                float o0 = acc[i][j][rr * 2 + 0] + bv0.x;
                float o1 = acc[i][j][rr * 2 + 1] + bv0.y;
                float p0 = acc[i][j + 4][rr * 2 + 0] + bv1.x;
                float p1 = acc[i][j + 4][rr * 2 + 1] + bv1.y;
#pragma unroll
                for (int s = 0; s < 4; s++) {
                    o0 += rw0[s] * xv[s].x;  o1 += rw0[s] * xv[s].y;
                    p0 += rw1[s] * xv[s].x;  p1 += rw1[s] * xv[s].y;
                }
                float* ob = out + (size_t)m * DD + tlo * SD + dd;
                *(float2*)ob = make_float2(o0, o1);
                *(float2*)(ob + SD) = make_float2(p0, p1);
            }
        }
    }
}

// ---------------- launch ----------------
extern "C" void kernel_launch(void* const* d_in, const int* in_sizes, int n_in,
                              void* d_out, int out_size) {
    const float* x     = (const float*)d_in[0];
    const float* g     = (const float*)d_in[1];
    const float* b     = (const float*)d_in[2];
    const float* Wa    = (const float*)d_in[3];
    const float* ba    = (const float*)d_in[4];
    const float* Wh    = (const float*)d_in[5];
    const float* bh    = (const float*)d_in[6];
    const float* pre_a = (const float*)d_in[7];
    const float* pre_h = (const float*)d_in[8];
    const float* res_a = (const float*)d_in[9];
    const float* post_a= (const float*)d_in[10];
    const float* sc_a  = (const float*)d_in[11];
    const float* res_h = (const float*)d_in[12];
    const float* post_h= (const float*)d_in[13];
    const float* sc_h  = (const float*)d_in[14];
    const float* cm    = (const float*)d_in[15];
    float* out = (float*)d_out;

    cudaFuncSetAttribute(gemm_kernel, cudaFuncAttributeMaxDynamicSharedMemorySize, DYN_SMEM);

    prep_kernel<<<MROWS + WT_BLOCKS, 256>>>(x, g, b, Wa, Wh,
                                            pre_a, pre_h, post_a, sc_a, post_h, sc_h, cm);
    gemm_kernel<<<dim3(16, 128), 128, DYN_SMEM>>>(x, out, res_a, res_h,
                                                  post_a, sc_a, post_h, sc_h, cm, ba, bh);
}